// round 1
// baseline (speedup 1.0000x reference)
#include <cuda_runtime.h>

#define B_ 2
#define N_ 16384
#define S_ 4096
#define K_ 32
#define C0 67
#define C1 64
#define C2 64
#define C3 128
#define ST 36
#define FULLM 0xffffffffu

typedef unsigned long long ull;

__device__ __forceinline__ ull fma2(ull a, ull b, ull c){
    ull d;
    asm("fma.rn.f32x2 %0, %1, %2, %3;" : "=l"(d) : "l"(a), "l"(b), "l"(c));
    return d;
}
__device__ __forceinline__ ull pk(float lo, float hi){
    ull r; asm("mov.b64 %0, {%1,%2};" : "=l"(r) : "f"(lo), "f"(hi)); return r;
}
__device__ __forceinline__ float2 upk(ull v){
    float2 f; asm("mov.b64 {%0,%1}, %2;" : "=f"(f.x), "=f"(f.y) : "l"(v)); return f;
}

// ---------------- scratch (static device memory; no allocs) ----------------
__device__ __align__(16) float  d_pt[B_*N_*C1];        // points transposed [b][n][c]
__device__ __align__(16) float4 d_xyz4[B_*N_];         // (x,y,z,|p|^2)
__device__              int     d_knn[B_*S_*K_];
__device__ __align__(16) float  d_buf0[(size_t)B_*S_*C1*K_];   // layer0 raw out
__device__ __align__(16) float  d_buf1[(size_t)B_*S_*C2*K_];   // layer1 raw out
__device__              float   d_maxb[B_*S_*C3];
__device__              float   d_minb[B_*S_*C3];
__device__              float   d_ps0[4096*C1], d_pq0[4096*C1];
__device__              float   d_ps1[4096*C2], d_pq1[4096*C2];
__device__              float   d_ps2[8192*C3], d_pq2[8192*C3];
__device__              float   d_mean0[C1], d_istd0[C1];
__device__              float   d_mean1[C2], d_istd1[C2];
__device__              float   d_mean2[C3], d_istd2[C3];

// ---------------- transpose points (B,64,N) -> [b][n][c] ----------------
__global__ void k_tr(const float* __restrict__ pts){
    __shared__ float tile[32][33];
    int b = blockIdx.z, c0 = blockIdx.y*32, n0 = blockIdx.x*32;
    for (int j = threadIdx.y; j < 32; j += 8)
        tile[j][threadIdx.x] = pts[((size_t)(b*C1 + c0 + j))*N_ + n0 + threadIdx.x];
    __syncthreads();
    for (int j = threadIdx.y; j < 32; j += 8)
        d_pt[((size_t)(b*N_ + n0 + j))*C1 + c0 + threadIdx.x] = tile[threadIdx.x][j];
}

// ---------------- xyz4 precompute + new_xyz copy ----------------
__global__ void k_xyz(const float* __restrict__ xyz, float* __restrict__ out){
    int i = blockIdx.x*blockDim.x + threadIdx.x;
    if (i >= B_*N_) return;
    int b = i / N_, n = i % N_;
    float x = xyz[(b*3+0)*N_+n], y = xyz[(b*3+1)*N_+n], z = xyz[(b*3+2)*N_+n];
    d_xyz4[i] = make_float4(x, y, z, fmaf(z,z, fmaf(y,y, x*x)));
    if (n < S_){
        out[(b*3+0)*S_+n] = x;
        out[(b*3+1)*S_+n] = y;
        out[(b*3+2)*S_+n] = z;
    }
}

// ---------------- KNN: one warp per query, warp-distributed top-32 ----------------
__global__ void k_knn(){
    int wid  = (blockIdx.x*blockDim.x + threadIdx.x) >> 5;
    int lane = threadIdx.x & 31;
    if (wid >= B_*S_) return;
    int b = wid / S_, s = wid % S_;
    const float4* base = &d_xyz4[b*N_];
    float4 c4 = base[s];
    float cx = c4.x, cy = c4.y, cz = c4.z, cs = c4.w;

    // init: lane takes candidate n = lane
    float4 p = base[lane];
    float bd = (cs + p.w) - 2.0f*fmaf(cz,p.z, fmaf(cy,p.y, cx*p.x));
    int   bi = lane;
    float curmax = bd;
    #pragma unroll
    for (int off = 16; off; off >>= 1)
        curmax = fmaxf(curmax, __shfl_xor_sync(FULLM, curmax, off));

    for (int j = 1; j < N_/32; j++){
        int n = j*32 + lane;
        p = base[n];
        float d = (cs + p.w) - 2.0f*fmaf(cz,p.z, fmaf(cy,p.y, cx*p.x));
        unsigned m = __ballot_sync(FULLM, d < curmax);
        while (m){
            int src = __ffs(m) - 1; m &= m - 1;
            float cd = __shfl_sync(FULLM, d, src);
            if (cd < curmax){
                int cn = j*32 + src;
                // argmax over kept entries (ties: evict larger index)
                float v = bd; int who = lane; int vi = bi;
                #pragma unroll
                for (int off = 16; off; off >>= 1){
                    float ov  = __shfl_xor_sync(FULLM, v,   off);
                    int   ow  = __shfl_xor_sync(FULLM, who, off);
                    int   ovi = __shfl_xor_sync(FULLM, vi,  off);
                    if (ov > v || (ov == v && ovi > vi)) { v = ov; who = ow; vi = ovi; }
                }
                if (lane == who){ bd = cd; bi = cn; }
                float nm = bd;
                #pragma unroll
                for (int off = 16; off; off >>= 1)
                    nm = fmaxf(nm, __shfl_xor_sync(FULLM, nm, off));
                curmax = nm;
            }
        }
    }
    d_knn[wid*K_ + lane] = bi;
}

// ---------------- layer0: gather + GEMM(64x67 @ 67x32) + partial stats ----------------
__global__ void k_g0(const float* __restrict__ W0g){
    __shared__ __align__(16) float sx[2*C0*ST];
    __shared__ __align__(16) float sw[C0*64];
    __shared__ float ssum[C1], ssq[C1];
    int t = threadIdx.x;
    int bs0 = blockIdx.x*2;

    for (int e = t; e < C0*64; e += 128){
        int ci = e >> 6, co = e & 63;
        sw[e] = W0g[co*C0 + ci];
    }
    if (t < C1){ ssum[t] = 0.f; ssq[t] = 0.f; }

    { // gather: 2 threads per (s,k), 32 channels each
        int pair = t >> 1, half = t & 1;
        int s_l = pair >> 5, k = pair & 31;
        int bs = bs0 + s_l;
        int b = bs / S_, s = bs % S_;
        int idx = d_knn[bs*K_ + k];
        float* xrow = &sx[s_l*C0*ST];
        if (half == 0){
            float4 pc = d_xyz4[b*N_ + s];
            float4 pn = d_xyz4[b*N_ + idx];
            xrow[0*ST + k] = pn.x - pc.x;
            xrow[1*ST + k] = pn.y - pc.y;
            xrow[2*ST + k] = pn.z - pc.z;
        }
        const float4* prow = (const float4*)&d_pt[((size_t)(b*N_ + idx))*C1];
        #pragma unroll
        for (int q = 0; q < 8; q++){
            float4 v = prow[half*8 + q];
            int c = half*32 + q*4;
            xrow[(3+c+0)*ST + k] = v.x;
            xrow[(3+c+1)*ST + k] = v.y;
            xrow[(3+c+2)*ST + k] = v.z;
            xrow[(3+c+3)*ST + k] = v.w;
        }
    }
    __syncthreads();

    int s_l = t >> 6, tt = t & 63;
    int co_b = (tt & 7)*8, k_b = (tt >> 3)*4;
    const float* xrow = &sx[s_l*C0*ST];
    ull acc[8][2];
    #pragma unroll
    for (int j = 0; j < 8; j++){ acc[j][0] = 0ull; acc[j][1] = 0ull; }

    for (int ci = 0; ci < C0; ci++){
        float4 xk = *(const float4*)&xrow[ci*ST + k_b];
        ull x0 = pk(xk.x, xk.y), x1 = pk(xk.z, xk.w);
        float4 wa = *(const float4*)&sw[ci*64 + co_b];
        float4 wb = *(const float4*)&sw[ci*64 + co_b + 4];
        float wv[8] = {wa.x,wa.y,wa.z,wa.w, wb.x,wb.y,wb.z,wb.w};
        #pragma unroll
        for (int j = 0; j < 8; j++){
            ull w = pk(wv[j], wv[j]);
            acc[j][0] = fma2(w, x0, acc[j][0]);
            acc[j][1] = fma2(w, x1, acc[j][1]);
        }
    }

    int bs = bs0 + s_l;
    float* orow = &d_buf0[(size_t)bs*C1*K_];
    float ls[8], lq[8];
    #pragma unroll
    for (int j = 0; j < 8; j++){
        float2 a0 = upk(acc[j][0]), a1 = upk(acc[j][1]);
        float4 o = make_float4(a0.x, a0.y, a1.x, a1.y);
        *(float4*)&orow[(co_b+j)*K_ + k_b] = o;
        ls[j] = (o.x + o.y) + (o.z + o.w);
        lq[j] = fmaf(o.x,o.x, fmaf(o.y,o.y, fmaf(o.z,o.z, o.w*o.w)));
    }
    #pragma unroll
    for (int j = 0; j < 8; j++){
        atomicAdd(&ssum[co_b+j], ls[j]);
        atomicAdd(&ssq [co_b+j], lq[j]);
    }
    __syncthreads();
    if (t < C1){
        d_ps0[blockIdx.x*C1 + t] = ssum[t];
        d_pq0[blockIdx.x*C1 + t] = ssq[t];
    }
}

// ---------------- stats finalize ----------------
__global__ void k_stats(int which){
    const float *ps, *pq; float *mean, *istd; int nblk, C;
    if (which == 0){ ps = d_ps0; pq = d_pq0; mean = d_mean0; istd = d_istd0; nblk = 4096; C = 64; }
    else if (which == 1){ ps = d_ps1; pq = d_pq1; mean = d_mean1; istd = d_istd1; nblk = 4096; C = 64; }
    else { ps = d_ps2; pq = d_pq2; mean = d_mean2; istd = d_istd2; nblk = 8192; C = 128; }
    int c = blockIdx.x;
    __shared__ float rs[256], rq[256];
    float s = 0.f, q = 0.f;
    for (int i = threadIdx.x; i < nblk; i += 256){ s += ps[i*C + c]; q += pq[i*C + c]; }
    rs[threadIdx.x] = s; rq[threadIdx.x] = q;
    __syncthreads();
    for (int o = 128; o; o >>= 1){
        if (threadIdx.x < o){ rs[threadIdx.x] += rs[threadIdx.x+o]; rq[threadIdx.x] += rq[threadIdx.x+o]; }
        __syncthreads();
    }
    if (threadIdx.x == 0){
        float cnt = (float)(B_*S_*K_);
        float m = rs[0] / cnt;
        float v = rq[0] / cnt - m*m;
        mean[c] = m;
        istd[c] = rsqrtf(v + 1e-5f);
    }
}

// ---------------- layer1: bn0+act on load, GEMM(64x64), partial stats ----------------
__global__ void k_g1(const float* __restrict__ W1g, const float* __restrict__ g0,
                     const float* __restrict__ b0){
    __shared__ __align__(16) float sx[2*C1*ST];
    __shared__ __align__(16) float sw[C1*64];
    __shared__ float ssum[C2], ssq[C2];
    __shared__ float sa[C1], sb[C1];
    int t = threadIdx.x;
    int bs0 = blockIdx.x*2;

    for (int e = t; e < C1*64; e += 128){
        int ci = e >> 6, co = e & 63;
        sw[e] = W1g[co*C1 + ci];
    }
    if (t < C1){
        float a = d_istd0[t]*g0[t];
        sa[t] = a;
        sb[t] = fmaf(-d_mean0[t], a, b0[t]);
    }
    if (t < C2){ ssum[t] = 0.f; ssq[t] = 0.f; }
    __syncthreads();

    for (int s_l = 0; s_l < 2; s_l++){
        const float4* src = (const float4*)&d_buf0[(size_t)(bs0+s_l)*C1*K_];
        float* xrow = &sx[s_l*C1*ST];
        for (int e = t; e < 512; e += 128){
            float4 v = src[e];
            int ci = e >> 3, k = (e & 7)*4;
            float a = sa[ci], bb = sb[ci], r;
            r = fmaf(v.x,a,bb); v.x = r >= 0.f ? r : 0.1f*r;
            r = fmaf(v.y,a,bb); v.y = r >= 0.f ? r : 0.1f*r;
            r = fmaf(v.z,a,bb); v.z = r >= 0.f ? r : 0.1f*r;
            r = fmaf(v.w,a,bb); v.w = r >= 0.f ? r : 0.1f*r;
            *(float4*)&xrow[ci*ST + k] = v;
        }
    }
    __syncthreads();

    int s_l = t >> 6, tt = t & 63;
    int co_b = (tt & 7)*8, k_b = (tt >> 3)*4;
    const float* xrow = &sx[s_l*C1*ST];
    ull acc[8][2];
    #pragma unroll
    for (int j = 0; j < 8; j++){ acc[j][0] = 0ull; acc[j][1] = 0ull; }

    for (int ci = 0; ci < C1; ci++){
        float4 xk = *(const float4*)&xrow[ci*ST + k_b];
        ull x0 = pk(xk.x, xk.y), x1 = pk(xk.z, xk.w);
        float4 wa = *(const float4*)&sw[ci*64 + co_b];
        float4 wb = *(const float4*)&sw[ci*64 + co_b + 4];
        float wv[8] = {wa.x,wa.y,wa.z,wa.w, wb.x,wb.y,wb.z,wb.w};
        #pragma unroll
        for (int j = 0; j < 8; j++){
            ull w = pk(wv[j], wv[j]);
            acc[j][0] = fma2(w, x0, acc[j][0]);
            acc[j][1] = fma2(w, x1, acc[j][1]);
        }
    }

    int bs = bs0 + s_l;
    float* orow = &d_buf1[(size_t)bs*C2*K_];
    float ls[8], lq[8];
    #pragma unroll
    for (int j = 0; j < 8; j++){
        float2 a0 = upk(acc[j][0]), a1 = upk(acc[j][1]);
        float4 o = make_float4(a0.x, a0.y, a1.x, a1.y);
        *(float4*)&orow[(co_b+j)*K_ + k_b] = o;
        ls[j] = (o.x + o.y) + (o.z + o.w);
        lq[j] = fmaf(o.x,o.x, fmaf(o.y,o.y, fmaf(o.z,o.z, o.w*o.w)));
    }
    #pragma unroll
    for (int j = 0; j < 8; j++){
        atomicAdd(&ssum[co_b+j], ls[j]);
        atomicAdd(&ssq [co_b+j], lq[j]);
    }
    __syncthreads();
    if (t < C2){
        d_ps1[blockIdx.x*C2 + t] = ssum[t];
        d_pq1[blockIdx.x*C2 + t] = ssq[t];
    }
}

// ---------------- layer2: bn1+act, GEMM(128x64), in-block max/min over k ----------------
__global__ void k_g2(const float* __restrict__ W2g, const float* __restrict__ g1,
                     const float* __restrict__ b1){
    __shared__ __align__(16) float sx[C2*ST];      // reused as reduction buffer
    __shared__ __align__(16) float sw[C2*C3];
    __shared__ float sa[C2], sb[C2];
    __shared__ float ssum[C3], ssq[C3];
    int t = threadIdx.x;
    int bs = blockIdx.x;

    for (int e = t; e < C2*C3; e += 128){
        int ci = e >> 7, co = e & 127;
        sw[e] = W2g[co*C2 + ci];
    }
    if (t < C2){
        float a = d_istd1[t]*g1[t];
        sa[t] = a;
        sb[t] = fmaf(-d_mean1[t], a, b1[t]);
    }
    if (t < C3){ ssum[t] = 0.f; ssq[t] = 0.f; }
    __syncthreads();

    {
        const float4* src = (const float4*)&d_buf1[(size_t)bs*C2*K_];
        for (int e = t; e < 512; e += 128){
            float4 v = src[e];
            int ci = e >> 3, k = (e & 7)*4;
            float a = sa[ci], bb = sb[ci], r;
            r = fmaf(v.x,a,bb); v.x = r >= 0.f ? r : 0.1f*r;
            r = fmaf(v.y,a,bb); v.y = r >= 0.f ? r : 0.1f*r;
            r = fmaf(v.z,a,bb); v.z = r >= 0.f ? r : 0.1f*r;
            r = fmaf(v.w,a,bb); v.w = r >= 0.f ? r : 0.1f*r;
            *(float4*)&sx[ci*ST + k] = v;
        }
    }
    __syncthreads();

    int co_b = (t & 15)*8, k_b = (t >> 4)*4, kb = t >> 4;
    ull acc[8][2];
    #pragma unroll
    for (int j = 0; j < 8; j++){ acc[j][0] = 0ull; acc[j][1] = 0ull; }

    for (int ci = 0; ci < C2; ci++){
        float4 xk = *(const float4*)&sx[ci*ST + k_b];
        ull x0 = pk(xk.x, xk.y), x1 = pk(xk.z, xk.w);
        float4 wa = *(const float4*)&sw[ci*C3 + co_b];
        float4 wb = *(const float4*)&sw[ci*C3 + co_b + 4];
        float wv[8] = {wa.x,wa.y,wa.z,wa.w, wb.x,wb.y,wb.z,wb.w};
        #pragma unroll
        for (int j = 0; j < 8; j++){
            ull w = pk(wv[j], wv[j]);
            acc[j][0] = fma2(w, x0, acc[j][0]);
            acc[j][1] = fma2(w, x1, acc[j][1]);
        }
    }

    float lmx[8], lmn[8], ls[8], lq[8];
    #pragma unroll
    for (int j = 0; j < 8; j++){
        float2 a0 = upk(acc[j][0]), a1 = upk(acc[j][1]);
        lmx[j] = fmaxf(fmaxf(a0.x,a0.y), fmaxf(a1.x,a1.y));
        lmn[j] = fminf(fminf(a0.x,a0.y), fminf(a1.x,a1.y));
        ls[j]  = (a0.x + a0.y) + (a1.x + a1.y);
        lq[j]  = fmaf(a0.x,a0.x, fmaf(a0.y,a0.y, fmaf(a1.x,a1.x, a1.y*a1.y)));
    }
    __syncthreads();   // all sx reads done; reuse as reduction buffer
    float* red = sx;   // [0,1024) = max, [1024,2048) = min
    #pragma unroll
    for (int j = 0; j < 8; j++){
        red[(co_b+j)*8 + kb]        = lmx[j];
        red[1024 + (co_b+j)*8 + kb] = lmn[j];
        atomicAdd(&ssum[co_b+j], ls[j]);
        atomicAdd(&ssq [co_b+j], lq[j]);
    }
    __syncthreads();
    if (t < C3){
        float mx = red[t*8], mn = red[1024 + t*8];
        #pragma unroll
        for (int q = 1; q < 8; q++){
            mx = fmaxf(mx, red[t*8 + q]);
            mn = fminf(mn, red[1024 + t*8 + q]);
        }
        d_maxb[bs*C3 + t] = mx;
        d_minb[bs*C3 + t] = mn;
        d_ps2[bs*C3 + t] = ssum[t];
        d_pq2[bs*C3 + t] = ssq[t];
    }
}

// ---------------- final: bn2 + act on max/min, write new_points ----------------
__global__ void k_final(const float* __restrict__ g2, const float* __restrict__ b2,
                        float* __restrict__ out){
    int o = blockIdx.x*blockDim.x + threadIdx.x;
    if (o >= B_*C3*S_) return;
    int s  = o & (S_ - 1);
    int co = (o >> 12) & 127;
    int b  = o >> 19;
    float a = d_istd2[co]*g2[co];
    float base = fmaf(-d_mean2[co], a, b2[co]);
    int bs = b*S_ + s;
    float yv = (a > 0.f) ? d_maxb[bs*C3 + co] : ((a < 0.f) ? d_minb[bs*C3 + co] : 0.f);
    float r = fmaf(yv, a, base);
    out[B_*3*S_ + o] = r >= 0.f ? r : 0.1f*r;
}

extern "C" void kernel_launch(void* const* d_in, const int* in_sizes, int n_in,
                              void* d_out, int out_size){
    const float* xyz    = (const float*)d_in[0];
    const float* points = (const float*)d_in[1];
    const float* W0     = (const float*)d_in[2];
    const float* W1     = (const float*)d_in[3];
    const float* W2     = (const float*)d_in[4];
    const float* g0     = (const float*)d_in[5];
    const float* b0     = (const float*)d_in[6];
    const float* g1     = (const float*)d_in[7];
    const float* b1     = (const float*)d_in[8];
    const float* g2     = (const float*)d_in[9];
    const float* b2     = (const float*)d_in[10];
    float* out = (float*)d_out;

    k_tr  <<<dim3(N_/32, C1/32, B_), dim3(32,8)>>>(points);
    k_xyz <<<(B_*N_ + 255)/256, 256>>>(xyz, out);
    k_knn <<<(B_*S_)/8, 256>>>();
    k_g0  <<<B_*S_/2, 128>>>(W0);
    k_stats<<<64, 256>>>(0);
    k_g1  <<<B_*S_/2, 128>>>(W1, g0, b0);
    k_stats<<<64, 256>>>(1);
    k_g2  <<<B_*S_, 128>>>(W2, g1, b1);
    k_stats<<<128, 256>>>(2);
    k_final<<<(B_*C3*S_ + 255)/256, 256>>>(g2, b2, out);
}

// round 2
// speedup vs baseline: 2.0435x; 2.0435x over previous
#include <cuda_runtime.h>

#define B_ 2
#define N_ 16384
#define S_ 4096
#define K_ 32
#define C0 67
#define C1 64
#define C2 64
#define C3 128
#define ST 36
#define FULLM 0xffffffffu

typedef unsigned long long ull;

__device__ __forceinline__ ull fma2(ull a, ull b, ull c){
    ull d;
    asm("fma.rn.f32x2 %0, %1, %2, %3;" : "=l"(d) : "l"(a), "l"(b), "l"(c));
    return d;
}
__device__ __forceinline__ ull pk(float lo, float hi){
    ull r; asm("mov.b64 %0, {%1,%2};" : "=l"(r) : "f"(lo), "f"(hi)); return r;
}
__device__ __forceinline__ float2 upk(ull v){
    float2 f; asm("mov.b64 {%0,%1}, %2;" : "=f"(f.x), "=f"(f.y) : "l"(v)); return f;
}

// ---------------- scratch ----------------
__device__ __align__(16) float  d_pt[B_*N_*C1];
__device__ __align__(16) float4 d_xyz4[B_*N_];
__device__              int     d_knn[B_*S_*K_];
__device__ __align__(16) float  d_buf0[(size_t)B_*S_*C1*K_];
__device__ __align__(16) float  d_buf1[(size_t)B_*S_*C2*K_];
__device__              float   d_maxb[B_*S_*C3];
__device__              float   d_minb[B_*S_*C3];
__device__              float   d_ps0[4096*C1], d_pq0[4096*C1];
__device__              float   d_ps1[4096*C2], d_pq1[4096*C2];
__device__              float   d_ps2[8192*C3], d_pq2[8192*C3];
__device__              float   d_mean0[C1], d_istd0[C1];
__device__              float   d_mean1[C2], d_istd1[C2];
__device__              float   d_mean2[C3], d_istd2[C3];

// ---------------- transpose points ----------------
__global__ void k_tr(const float* __restrict__ pts){
    __shared__ float tile[32][33];
    int b = blockIdx.z, c0 = blockIdx.y*32, n0 = blockIdx.x*32;
    for (int j = threadIdx.y; j < 32; j += 8)
        tile[j][threadIdx.x] = pts[((size_t)(b*C1 + c0 + j))*N_ + n0 + threadIdx.x];
    __syncthreads();
    for (int j = threadIdx.y; j < 32; j += 8)
        d_pt[((size_t)(b*N_ + n0 + j))*C1 + c0 + threadIdx.x] = tile[threadIdx.x][j];
}

// ---------------- xyz4 + new_xyz ----------------
__global__ void k_xyz(const float* __restrict__ xyz, float* __restrict__ out){
    int i = blockIdx.x*blockDim.x + threadIdx.x;
    if (i >= B_*N_) return;
    int b = i / N_, n = i % N_;
    float x = xyz[(b*3+0)*N_+n], y = xyz[(b*3+1)*N_+n], z = xyz[(b*3+2)*N_+n];
    d_xyz4[i] = make_float4(x, y, z, fmaf(z,z, fmaf(y,y, x*x)));
    if (n < S_){
        out[(b*3+0)*S_+n] = x;
        out[(b*3+1)*S_+n] = y;
        out[(b*3+2)*S_+n] = z;
    }
}

// ---------------- KNN: warp per query, sorted-across-lanes top-32 ----------------
__global__ void k_knn(){
    int wid  = (blockIdx.x*blockDim.x + threadIdx.x) >> 5;
    int lane = threadIdx.x & 31;
    int b = wid / S_, s = wid % S_;
    const float4* base = &d_xyz4[b*N_];
    float4 c4 = base[s];
    float cx = c4.x, cy = c4.y, cz = c4.z, cs = c4.w;

    // lane L holds L-th smallest key; key = order-preserving uint of distance
    unsigned bkey = 0xFFFFFFFFu;   // +inf sentinel
    int      bi   = 0;
    unsigned curmax = 0xFFFFFFFFu;

    #pragma unroll 2
    for (int j = 0; j < N_/32; j++){
        float4 p = base[j*32 + lane];
        float d = (cs + p.w) - 2.0f*fmaf(cz,p.z, fmaf(cy,p.y, cx*p.x));
        unsigned u = __float_as_uint(d);
        unsigned key = u ^ (unsigned)(((int)u >> 31) | 0x80000000);
        unsigned m = __ballot_sync(FULLM, key < curmax);
        while (m){
            int src = __ffs(m) - 1; m &= m - 1;
            unsigned ck = __shfl_sync(FULLM, key, src);
            if (ck < curmax){
                int cn = j*32 + src;
                unsigned pk_ = __shfl_up_sync(FULLM, bkey, 1);
                int      pi_ = __shfl_up_sync(FULLM, bi, 1);
                bool shift = (bkey > ck);          // strict: stable vs ties
                unsigned sm_ = __ballot_sync(FULLM, shift);
                int first = __ffs(sm_) - 1;
                if (shift){
                    if (lane == first){ bkey = ck; bi = cn; }
                    else              { bkey = pk_; bi = pi_; }
                }
                curmax = __shfl_sync(FULLM, bkey, 31);
            }
        }
    }
    d_knn[wid*K_ + lane] = bi;
}

// ---------------- layer0: gather + GEMM, 8x8 tile per thread, warp per point ----------------
__global__ void __launch_bounds__(128, 4) k_g0(const float* __restrict__ W0g){
    extern __shared__ float dyn[];
    float* sx = dyn;                 // 4 * C0 * ST
    float* sw = dyn + 4*C0*ST;       // C0 * 64
    __shared__ float ssum[C1], ssq[C1];
    int t = threadIdx.x;
    int bs0 = blockIdx.x*4;

    for (int e = t; e < C0*64; e += 128){
        int ci = e >> 6, co = e & 63;
        sw[e] = W0g[co*C0 + ci];
    }
    if (t < C1){ ssum[t] = 0.f; ssq[t] = 0.f; }

    { // gather: 1 thread per (point, k)
        int s_l = t >> 5, k = t & 31;
        int bs = bs0 + s_l;
        int b = bs / S_, s = bs % S_;
        int idx = d_knn[bs*K_ + k];
        float* xr = &sx[s_l*C0*ST];
        float4 pc = d_xyz4[b*N_ + s];
        float4 pn = d_xyz4[b*N_ + idx];
        xr[0*ST + k] = pn.x - pc.x;
        xr[1*ST + k] = pn.y - pc.y;
        xr[2*ST + k] = pn.z - pc.z;
        const float4* prow = (const float4*)&d_pt[((size_t)(b*N_ + idx))*C1];
        #pragma unroll
        for (int q = 0; q < 16; q++){
            float4 v = prow[q];
            int c = 3 + q*4;
            xr[(c+0)*ST + k] = v.x;
            xr[(c+1)*ST + k] = v.y;
            xr[(c+2)*ST + k] = v.z;
            xr[(c+3)*ST + k] = v.w;
        }
    }
    __syncthreads();

    int lane = t & 31, wp = t >> 5;
    int kq = lane & 3, cog = lane >> 2;
    const float* xb_ = &sx[wp*C0*ST + kq*8];
    const float* wb_ = sw + cog*8;
    ull acc[8][4];
    #pragma unroll
    for (int j = 0; j < 8; j++){ acc[j][0]=0; acc[j][1]=0; acc[j][2]=0; acc[j][3]=0; }

    for (int ci = 0; ci < C0; ci++){
        float4 xa = *(const float4*)(xb_ + ci*ST);
        float4 xc = *(const float4*)(xb_ + ci*ST + 4);
        ull x0 = pk(xa.x,xa.y), x1 = pk(xa.z,xa.w);
        ull x2 = pk(xc.x,xc.y), x3 = pk(xc.z,xc.w);
        float4 wa = *(const float4*)(wb_ + ci*64);
        float4 wc = *(const float4*)(wb_ + ci*64 + 4);
        float wv[8] = {wa.x,wa.y,wa.z,wa.w, wc.x,wc.y,wc.z,wc.w};
        #pragma unroll
        for (int j = 0; j < 8; j++){
            ull w2 = pk(wv[j], wv[j]);
            acc[j][0] = fma2(w2, x0, acc[j][0]);
            acc[j][1] = fma2(w2, x1, acc[j][1]);
            acc[j][2] = fma2(w2, x2, acc[j][2]);
            acc[j][3] = fma2(w2, x3, acc[j][3]);
        }
    }

    int bs = bs0 + wp;
    float* orow = &d_buf0[(size_t)bs*C1*K_];
    float ls[8], lq[8];
    #pragma unroll
    for (int j = 0; j < 8; j++){
        float2 a0 = upk(acc[j][0]), a1 = upk(acc[j][1]);
        float2 a2 = upk(acc[j][2]), a3 = upk(acc[j][3]);
        *(float4*)&orow[(cog*8+j)*K_ + kq*8]     = make_float4(a0.x,a0.y,a1.x,a1.y);
        *(float4*)&orow[(cog*8+j)*K_ + kq*8 + 4] = make_float4(a2.x,a2.y,a3.x,a3.y);
        ls[j] = ((a0.x+a0.y)+(a1.x+a1.y)) + ((a2.x+a2.y)+(a3.x+a3.y));
        float q0 = fmaf(a0.x,a0.x, fmaf(a0.y,a0.y, fmaf(a1.x,a1.x, a1.y*a1.y)));
        lq[j] = fmaf(a2.x,a2.x, fmaf(a2.y,a2.y, fmaf(a3.x,a3.x, fmaf(a3.y,a3.y, q0))));
    }
    #pragma unroll
    for (int j = 0; j < 8; j++){
        ls[j] += __shfl_xor_sync(FULLM, ls[j], 1);
        ls[j] += __shfl_xor_sync(FULLM, ls[j], 2);
        lq[j] += __shfl_xor_sync(FULLM, lq[j], 1);
        lq[j] += __shfl_xor_sync(FULLM, lq[j], 2);
    }
    if (kq == 0){
        #pragma unroll
        for (int j = 0; j < 8; j++){
            atomicAdd(&ssum[cog*8+j], ls[j]);
            atomicAdd(&ssq [cog*8+j], lq[j]);
        }
    }
    __syncthreads();
    if (t < C1){
        d_ps0[blockIdx.x*C1 + t] = ssum[t];
        d_pq0[blockIdx.x*C1 + t] = ssq[t];
    }
}

// ---------------- stats finalize ----------------
__global__ void k_stats(int which){
    const float *ps, *pq; float *mean, *istd; int nblk, C;
    if (which == 0){ ps = d_ps0; pq = d_pq0; mean = d_mean0; istd = d_istd0; nblk = 2048; C = 64; }
    else if (which == 1){ ps = d_ps1; pq = d_pq1; mean = d_mean1; istd = d_istd1; nblk = 2048; C = 64; }
    else { ps = d_ps2; pq = d_pq2; mean = d_mean2; istd = d_istd2; nblk = 4096; C = 128; }
    int c = blockIdx.x;
    __shared__ float rs[256], rq[256];
    float s = 0.f, q = 0.f;
    for (int i = threadIdx.x; i < nblk; i += 256){ s += ps[i*C + c]; q += pq[i*C + c]; }
    rs[threadIdx.x] = s; rq[threadIdx.x] = q;
    __syncthreads();
    for (int o = 128; o; o >>= 1){
        if (threadIdx.x < o){ rs[threadIdx.x] += rs[threadIdx.x+o]; rq[threadIdx.x] += rq[threadIdx.x+o]; }
        __syncthreads();
    }
    if (threadIdx.x == 0){
        float cnt = (float)(B_*S_*K_);
        float m = rs[0] / cnt;
        float v = rq[0] / cnt - m*m;
        mean[c] = m;
        istd[c] = rsqrtf(v + 1e-5f);
    }
}

// ---------------- layer1 ----------------
__global__ void __launch_bounds__(128, 4) k_g1(const float* __restrict__ W1g,
                     const float* __restrict__ g0, const float* __restrict__ b0){
    extern __shared__ float dyn[];
    float* sx = dyn;                 // 4 * C1 * ST
    float* sw = dyn + 4*C1*ST;       // C1 * 64
    __shared__ float ssum[C2], ssq[C2], sa[C1], sb[C1];
    int t = threadIdx.x;
    int bs0 = blockIdx.x*4;

    for (int e = t; e < C1*64; e += 128){
        int ci = e >> 6, co = e & 63;
        sw[e] = W1g[co*C1 + ci];
    }
    if (t < C1){
        float a = d_istd0[t]*g0[t];
        sa[t] = a;
        sb[t] = fmaf(-d_mean0[t], a, b0[t]);
        ssum[t] = 0.f; ssq[t] = 0.f;
    }
    __syncthreads();

    {
        const float4* src = (const float4*)&d_buf0[(size_t)bs0*C1*K_];
        for (int e = t; e < 2048; e += 128){
            float4 v = src[e];
            int p = e >> 9, r2 = e & 511;
            int ci = r2 >> 3, k4 = (r2 & 7)*4;
            float a = sa[ci], bb = sb[ci], r;
            r = fmaf(v.x,a,bb); v.x = r >= 0.f ? r : 0.1f*r;
            r = fmaf(v.y,a,bb); v.y = r >= 0.f ? r : 0.1f*r;
            r = fmaf(v.z,a,bb); v.z = r >= 0.f ? r : 0.1f*r;
            r = fmaf(v.w,a,bb); v.w = r >= 0.f ? r : 0.1f*r;
            *(float4*)&sx[p*C1*ST + ci*ST + k4] = v;
        }
    }
    __syncthreads();

    int lane = t & 31, wp = t >> 5;
    int kq = lane & 3, cog = lane >> 2;
    const float* xb_ = &sx[wp*C1*ST + kq*8];
    const float* wb_ = sw + cog*8;
    ull acc[8][4];
    #pragma unroll
    for (int j = 0; j < 8; j++){ acc[j][0]=0; acc[j][1]=0; acc[j][2]=0; acc[j][3]=0; }

    for (int ci = 0; ci < C1; ci++){
        float4 xa = *(const float4*)(xb_ + ci*ST);
        float4 xc = *(const float4*)(xb_ + ci*ST + 4);
        ull x0 = pk(xa.x,xa.y), x1 = pk(xa.z,xa.w);
        ull x2 = pk(xc.x,xc.y), x3 = pk(xc.z,xc.w);
        float4 wa = *(const float4*)(wb_ + ci*64);
        float4 wc = *(const float4*)(wb_ + ci*64 + 4);
        float wv[8] = {wa.x,wa.y,wa.z,wa.w, wc.x,wc.y,wc.z,wc.w};
        #pragma unroll
        for (int j = 0; j < 8; j++){
            ull w2 = pk(wv[j], wv[j]);
            acc[j][0] = fma2(w2, x0, acc[j][0]);
            acc[j][1] = fma2(w2, x1, acc[j][1]);
            acc[j][2] = fma2(w2, x2, acc[j][2]);
            acc[j][3] = fma2(w2, x3, acc[j][3]);
        }
    }

    int bs = bs0 + wp;
    float* orow = &d_buf1[(size_t)bs*C2*K_];
    float ls[8], lq[8];
    #pragma unroll
    for (int j = 0; j < 8; j++){
        float2 a0 = upk(acc[j][0]), a1 = upk(acc[j][1]);
        float2 a2 = upk(acc[j][2]), a3 = upk(acc[j][3]);
        *(float4*)&orow[(cog*8+j)*K_ + kq*8]     = make_float4(a0.x,a0.y,a1.x,a1.y);
        *(float4*)&orow[(cog*8+j)*K_ + kq*8 + 4] = make_float4(a2.x,a2.y,a3.x,a3.y);
        ls[j] = ((a0.x+a0.y)+(a1.x+a1.y)) + ((a2.x+a2.y)+(a3.x+a3.y));
        float q0 = fmaf(a0.x,a0.x, fmaf(a0.y,a0.y, fmaf(a1.x,a1.x, a1.y*a1.y)));
        lq[j] = fmaf(a2.x,a2.x, fmaf(a2.y,a2.y, fmaf(a3.x,a3.x, fmaf(a3.y,a3.y, q0))));
    }
    #pragma unroll
    for (int j = 0; j < 8; j++){
        ls[j] += __shfl_xor_sync(FULLM, ls[j], 1);
        ls[j] += __shfl_xor_sync(FULLM, ls[j], 2);
        lq[j] += __shfl_xor_sync(FULLM, lq[j], 1);
        lq[j] += __shfl_xor_sync(FULLM, lq[j], 2);
    }
    if (kq == 0){
        #pragma unroll
        for (int j = 0; j < 8; j++){
            atomicAdd(&ssum[cog*8+j], ls[j]);
            atomicAdd(&ssq [cog*8+j], lq[j]);
        }
    }
    __syncthreads();
    if (t < C2){
        d_ps1[blockIdx.x*C2 + t] = ssum[t];
        d_pq1[blockIdx.x*C2 + t] = ssq[t];
    }
}

// ---------------- layer2: 2 points/block, 2 warps/point, max/min over k ----------------
__global__ void __launch_bounds__(128, 4) k_g2(const float* __restrict__ W2g,
                     const float* __restrict__ g1, const float* __restrict__ b1){
    extern __shared__ float dyn[];
    float* sx = dyn;                 // 2 * C2 * ST
    float* sw = dyn + 2*C2*ST;       // C2 * 128
    __shared__ float sa[C2], sb[C2], ssum[C3], ssq[C3];
    int t = threadIdx.x;
    int bs0 = blockIdx.x*2;

    for (int e = t; e < C2*C3; e += 128){
        int ci = e >> 7, co = e & 127;
        sw[e] = W2g[co*C2 + ci];
    }
    if (t < C2){
        float a = d_istd1[t]*g1[t];
        sa[t] = a;
        sb[t] = fmaf(-d_mean1[t], a, b1[t]);
    }
    if (t < C3){ ssum[t] = 0.f; ssq[t] = 0.f; }
    __syncthreads();

    {
        const float4* src = (const float4*)&d_buf1[(size_t)bs0*C2*K_];
        for (int e = t; e < 1024; e += 128){
            float4 v = src[e];
            int p = e >> 9, r2 = e & 511;
            int ci = r2 >> 3, k4 = (r2 & 7)*4;
            float a = sa[ci], bb = sb[ci], r;
            r = fmaf(v.x,a,bb); v.x = r >= 0.f ? r : 0.1f*r;
            r = fmaf(v.y,a,bb); v.y = r >= 0.f ? r : 0.1f*r;
            r = fmaf(v.z,a,bb); v.z = r >= 0.f ? r : 0.1f*r;
            r = fmaf(v.w,a,bb); v.w = r >= 0.f ? r : 0.1f*r;
            *(float4*)&sx[p*C2*ST + ci*ST + k4] = v;
        }
    }
    __syncthreads();

    int lane = t & 31, wp = t >> 5;
    int pt = wp >> 1, half = wp & 1;
    int kq = lane & 3, cog = lane >> 2;
    const float* xb_ = &sx[pt*C2*ST + kq*8];
    const float* wb_ = sw + half*64 + cog*8;
    ull acc[8][4];
    #pragma unroll
    for (int j = 0; j < 8; j++){ acc[j][0]=0; acc[j][1]=0; acc[j][2]=0; acc[j][3]=0; }

    for (int ci = 0; ci < C2; ci++){
        float4 xa = *(const float4*)(xb_ + ci*ST);
        float4 xc = *(const float4*)(xb_ + ci*ST + 4);
        ull x0 = pk(xa.x,xa.y), x1 = pk(xa.z,xa.w);
        ull x2 = pk(xc.x,xc.y), x3 = pk(xc.z,xc.w);
        float4 wa = *(const float4*)(wb_ + ci*128);
        float4 wc = *(const float4*)(wb_ + ci*128 + 4);
        float wv[8] = {wa.x,wa.y,wa.z,wa.w, wc.x,wc.y,wc.z,wc.w};
        #pragma unroll
        for (int j = 0; j < 8; j++){
            ull w2 = pk(wv[j], wv[j]);
            acc[j][0] = fma2(w2, x0, acc[j][0]);
            acc[j][1] = fma2(w2, x1, acc[j][1]);
            acc[j][2] = fma2(w2, x2, acc[j][2]);
            acc[j][3] = fma2(w2, x3, acc[j][3]);
        }
    }

    int bs = bs0 + pt;
    float lmx[8], lmn[8], ls[8], lq[8];
    #pragma unroll
    for (int j = 0; j < 8; j++){
        float2 a0 = upk(acc[j][0]), a1 = upk(acc[j][1]);
        float2 a2 = upk(acc[j][2]), a3 = upk(acc[j][3]);
        lmx[j] = fmaxf(fmaxf(fmaxf(a0.x,a0.y),fmaxf(a1.x,a1.y)),
                       fmaxf(fmaxf(a2.x,a2.y),fmaxf(a3.x,a3.y)));
        lmn[j] = fminf(fminf(fminf(a0.x,a0.y),fminf(a1.x,a1.y)),
                       fminf(fminf(a2.x,a2.y),fminf(a3.x,a3.y)));
        ls[j] = ((a0.x+a0.y)+(a1.x+a1.y)) + ((a2.x+a2.y)+(a3.x+a3.y));
        float q0 = fmaf(a0.x,a0.x, fmaf(a0.y,a0.y, fmaf(a1.x,a1.x, a1.y*a1.y)));
        lq[j] = fmaf(a2.x,a2.x, fmaf(a2.y,a2.y, fmaf(a3.x,a3.x, fmaf(a3.y,a3.y, q0))));
    }
    #pragma unroll
    for (int j = 0; j < 8; j++){
        lmx[j] = fmaxf(lmx[j], __shfl_xor_sync(FULLM, lmx[j], 1));
        lmx[j] = fmaxf(lmx[j], __shfl_xor_sync(FULLM, lmx[j], 2));
        lmn[j] = fminf(lmn[j], __shfl_xor_sync(FULLM, lmn[j], 1));
        lmn[j] = fminf(lmn[j], __shfl_xor_sync(FULLM, lmn[j], 2));
        ls[j] += __shfl_xor_sync(FULLM, ls[j], 1);
        ls[j] += __shfl_xor_sync(FULLM, ls[j], 2);
        lq[j] += __shfl_xor_sync(FULLM, lq[j], 1);
        lq[j] += __shfl_xor_sync(FULLM, lq[j], 2);
    }
    if (kq == 0){
        #pragma unroll
        for (int j = 0; j < 8; j++){
            int co = half*64 + cog*8 + j;
            d_maxb[bs*C3 + co] = lmx[j];
            d_minb[bs*C3 + co] = lmn[j];
            atomicAdd(&ssum[co], ls[j]);
            atomicAdd(&ssq [co], lq[j]);
        }
    }
    __syncthreads();
    if (t < C3){
        d_ps2[blockIdx.x*C3 + t] = ssum[t];
        d_pq2[blockIdx.x*C3 + t] = ssq[t];
    }
}

// ---------------- final ----------------
__global__ void k_final(const float* __restrict__ g2, const float* __restrict__ b2,
                        float* __restrict__ out){
    int o = blockIdx.x*blockDim.x + threadIdx.x;
    if (o >= B_*C3*S_) return;
    int s  = o & (S_ - 1);
    int co = (o >> 12) & 127;
    int b  = o >> 19;
    float a = d_istd2[co]*g2[co];
    float base = fmaf(-d_mean2[co], a, b2[co]);
    int bs = b*S_ + s;
    float yv = (a > 0.f) ? d_maxb[bs*C3 + co] : ((a < 0.f) ? d_minb[bs*C3 + co] : 0.f);
    float r = fmaf(yv, a, base);
    out[B_*3*S_ + o] = r >= 0.f ? r : 0.1f*r;
}

extern "C" void kernel_launch(void* const* d_in, const int* in_sizes, int n_in,
                              void* d_out, int out_size){
    const float* xyz    = (const float*)d_in[0];
    const float* points = (const float*)d_in[1];
    const float* W0     = (const float*)d_in[2];
    const float* W1     = (const float*)d_in[3];
    const float* W2     = (const float*)d_in[4];
    const float* g0     = (const float*)d_in[5];
    const float* b0     = (const float*)d_in[6];
    const float* g1     = (const float*)d_in[7];
    const float* b1     = (const float*)d_in[8];
    const float* g2     = (const float*)d_in[9];
    const float* b2     = (const float*)d_in[10];
    float* out = (float*)d_out;

    const int smem0 = (4*C0*ST + C0*64) * 4;   // 55,744
    const int smem1 = (4*C1*ST + C1*64) * 4;   // 53,248
    const int smem2 = (2*C2*ST + C2*C3) * 4;   // 51,200
    cudaFuncSetAttribute(k_g0, cudaFuncAttributeMaxDynamicSharedMemorySize, smem0);
    cudaFuncSetAttribute(k_g1, cudaFuncAttributeMaxDynamicSharedMemorySize, smem1);
    cudaFuncSetAttribute(k_g2, cudaFuncAttributeMaxDynamicSharedMemorySize, smem2);

    k_tr  <<<dim3(N_/32, C1/32, B_), dim3(32,8)>>>(points);
    k_xyz <<<(B_*N_ + 255)/256, 256>>>(xyz, out);
    k_knn <<<(B_*S_)/8, 256>>>();
    k_g0  <<<B_*S_/4, 128, smem0>>>(W0);
    k_stats<<<64, 256>>>(0);
    k_g1  <<<B_*S_/4, 128, smem1>>>(W1, g0, b0);
    k_stats<<<64, 256>>>(1);
    k_g2  <<<B_*S_/2, 128, smem2>>>(W2, g1, b1);
    k_stats<<<128, 256>>>(2);
    k_final<<<(B_*C3*S_ + 255)/256, 256>>>(g2, b2, out);
}